// round 6
// baseline (speedup 1.0000x reference)
#include <cuda_runtime.h>
#include <cuda_bf16.h>
#include <math.h>
#include <stdint.h>

#define B_SZ  16
#define L_SZ  1024
#define DM    166
#define DI    332
#define DS    16
#define DCV   4
#define DTR   11
#define NLAY  3
#define XZW   (2*DI)        // 664
#define DBCW  (DTR + 2*DS)  // 43
#define ROWS  (B_SZ*L_SZ)   // 16384
#define EPSV  1e-5f
#define SEG   32
#define SLEN  (L_SZ/SEG)    // 32

// -------- scratch (device globals; no allocation allowed) --------
__device__ float g_hidden[ROWS*DM];
__device__ float g_resid [ROWS*DM];
__device__ float g_hnorm [ROWS*DM];
__device__ float g_xz    [ROWS*XZW];
__device__ float g_xc    [ROWS*DI];
__device__ float g_dbc   [ROWS*DBCW];
__device__ float g_dt    [ROWS*DI];
__device__ float g_y     [ROWS*DI];
__device__ float g_segP  [B_SZ*DI*SEG*DS];
__device__ float g_segH  [B_SZ*DI*SEG*DS];
__device__ float g_segS  [B_SZ*DI*SEG*DS];

// -------- fast transcendental helpers --------
__device__ __forceinline__ float fex2(float x) {
    float r; asm("ex2.approx.ftz.f32 %0, %1;" : "=f"(r) : "f"(x)); return r;
}
__device__ __forceinline__ float frcp(float x) {
    float r; asm("rcp.approx.ftz.f32 %0, %1;" : "=f"(r) : "f"(x)); return r;
}
#define LOG2E 1.44269504f
__device__ __forceinline__ float fsilu(float s) {
    return s * frcp(1.f + fex2(-LOG2E * s));
}

// ==================== split-bf16 HMMA GEMM (ldmatrix + double buffer) ====================
#define BM 128
#define BN 64
#define BK 32
#define LDK 40   // padded smem row (bf16): 80B stride -> conflict-free ldmatrix phases

__device__ __forceinline__ void mma_bf16(float* c, const uint32_t* a, uint32_t b0, uint32_t b1) {
    asm volatile(
        "mma.sync.aligned.m16n8k16.row.col.f32.bf16.bf16.f32 "
        "{%0,%1,%2,%3}, {%4,%5,%6,%7}, {%8,%9}, {%0,%1,%2,%3};"
        : "+f"(c[0]), "+f"(c[1]), "+f"(c[2]), "+f"(c[3])
        : "r"(a[0]), "r"(a[1]), "r"(a[2]), "r"(a[3]), "r"(b0), "r"(b1));
}
__device__ __forceinline__ void ldsm_x4(uint32_t* r, uint32_t addr) {
    asm volatile("ldmatrix.sync.aligned.m8n8.x4.shared.b16 {%0,%1,%2,%3}, [%4];"
        : "=r"(r[0]), "=r"(r[1]), "=r"(r[2]), "=r"(r[3]) : "r"(addr));
}

template<int K, bool NEVEN>
__global__ void __launch_bounds__(256) k_hgemm(const float* __restrict__ A,
                                               const float* __restrict__ W,
                                               float* __restrict__ C, int N) {
    __shared__ __nv_bfloat16 Ah[2][BM][LDK];
    __shared__ __nv_bfloat16 Al[2][BM][LDK];
    __shared__ __nv_bfloat16 Bh[2][BN][LDK];
    __shared__ __nv_bfloat16 Bl[2][BN][LDK];

    constexpr int KT = (K + BK - 1) / BK;
    int tid  = threadIdx.x;
    int wid  = tid >> 5;
    int lane = tid & 31;
    int wm = wid & 3;
    int wn = wid >> 2;
    int grp = lane >> 2;
    int tig = lane & 3;
    int m0 = blockIdx.y * BM;
    int n0 = blockIdx.x * BN;

    int arow = tid >> 4, acp = tid & 15;   // loader coords
    // ldmatrix lane addressing: q = lane>>3, rr = lane&7
    int lq = lane >> 3, lr = lane & 7;
    int frow = (lq & 1) * 8 + lr;          // row within 16-row tile
    int fcol = (lq >> 1) * 8;              // col offset within 16-col kstep

    uint32_t sAh = (uint32_t)__cvta_generic_to_shared(&Ah[0][0][0]);
    uint32_t sAl = (uint32_t)__cvta_generic_to_shared(&Al[0][0][0]);
    uint32_t sBh = (uint32_t)__cvta_generic_to_shared(&Bh[0][0][0]);
    uint32_t sBl = (uint32_t)__cvta_generic_to_shared(&Bl[0][0][0]);
    const uint32_t ABUF = BM*LDK*2, BBUF = BN*LDK*2;

    float acc[2][4][4];
#pragma unroll
    for (int i = 0; i < 2; i++)
#pragma unroll
        for (int j = 0; j < 4; j++)
#pragma unroll
            for (int q = 0; q < 4; q++) acc[i][j][q] = 0.f;

    float2 ra[8], rb[4];

    // ---- prologue: load tile 0 ----
#pragma unroll
    for (int i = 0; i < 8; i++) {
        int row = arow + i*16;
        int kg = acp*2;
        ra[i] = (kg < K) ? *(const float2*)(A + (size_t)(m0 + row)*K + kg)
                         : make_float2(0.f, 0.f);
    }
#pragma unroll
    for (int i = 0; i < 4; i++) {
        int row = arow + i*16;
        int kg = acp*2;
        int n = n0 + row;
        rb[i] = (n < N && kg < K) ? *(const float2*)(W + (size_t)n*K + kg)
                                  : make_float2(0.f, 0.f);
    }
#pragma unroll
    for (int i = 0; i < 8; i++) {
        int row = arow + i*16;
        __nv_bfloat16 h0 = __float2bfloat16(ra[i].x);
        __nv_bfloat16 h1 = __float2bfloat16(ra[i].y);
        Ah[0][row][acp*2]   = h0;
        Ah[0][row][acp*2+1] = h1;
        Al[0][row][acp*2]   = __float2bfloat16(ra[i].x - __bfloat162float(h0));
        Al[0][row][acp*2+1] = __float2bfloat16(ra[i].y - __bfloat162float(h1));
    }
#pragma unroll
    for (int i = 0; i < 4; i++) {
        int row = arow + i*16;
        __nv_bfloat16 h0 = __float2bfloat16(rb[i].x);
        __nv_bfloat16 h1 = __float2bfloat16(rb[i].y);
        Bh[0][row][acp*2]   = h0;
        Bh[0][row][acp*2+1] = h1;
        Bl[0][row][acp*2]   = __float2bfloat16(rb[i].x - __bfloat162float(h0));
        Bl[0][row][acp*2+1] = __float2bfloat16(rb[i].y - __bfloat162float(h1));
    }
    __syncthreads();

#pragma unroll 1
    for (int t = 0; t < KT; t++) {
        int buf = t & 1;
        // ---- issue next tile's LDGs ----
        if (t + 1 < KT) {
            int k0 = (t + 1) * BK;
#pragma unroll
            for (int i = 0; i < 8; i++) {
                int row = arow + i*16;
                int kg = k0 + acp*2;
                ra[i] = (kg < K) ? *(const float2*)(A + (size_t)(m0 + row)*K + kg)
                                 : make_float2(0.f, 0.f);
            }
#pragma unroll
            for (int i = 0; i < 4; i++) {
                int row = arow + i*16;
                int kg = k0 + acp*2;
                int n = n0 + row;
                rb[i] = (n < N && kg < K) ? *(const float2*)(W + (size_t)n*K + kg)
                                          : make_float2(0.f, 0.f);
            }
        }

        // ---- compute from buf via ldmatrix ----
        uint32_t aoff = buf * ABUF, boff = buf * BBUF;
#pragma unroll
        for (int ks = 0; ks < BK; ks += 16) {
            uint32_t ah[2][4], al[2][4], bh[2][4], bl[2][4];
#pragma unroll
            for (int i = 0; i < 2; i++) {
                uint32_t ro = (uint32_t)((wm*32 + i*16 + frow)*LDK + ks + fcol)*2;
                ldsm_x4(ah[i], sAh + aoff + ro);
                ldsm_x4(al[i], sAl + aoff + ro);
            }
#pragma unroll
            for (int jj = 0; jj < 2; jj++) {
                uint32_t ro = (uint32_t)((wn*32 + jj*16 + frow)*LDK + ks + fcol)*2;
                ldsm_x4(bh[jj], sBh + boff + ro);
                ldsm_x4(bl[jj], sBl + boff + ro);
            }
#pragma unroll
            for (int i = 0; i < 2; i++)
#pragma unroll
                for (int j = 0; j < 4; j++) {
                    int jj = j >> 1, sel = j & 1;
                    uint32_t b0h = bh[jj][sel], b1h = bh[jj][sel + 2];
                    uint32_t b0l = bl[jj][sel], b1l = bl[jj][sel + 2];
                    mma_bf16(acc[i][j], ah[i], b0h, b1h);
                    mma_bf16(acc[i][j], ah[i], b0l, b1l);
                    mma_bf16(acc[i][j], al[i], b0h, b1h);
                }
        }

        // ---- split + store next tile into other buffer ----
        if (t + 1 < KT) {
            int nb = (t + 1) & 1;
#pragma unroll
            for (int i = 0; i < 8; i++) {
                int row = arow + i*16;
                __nv_bfloat16 h0 = __float2bfloat16(ra[i].x);
                __nv_bfloat16 h1 = __float2bfloat16(ra[i].y);
                Ah[nb][row][acp*2]   = h0;
                Ah[nb][row][acp*2+1] = h1;
                Al[nb][row][acp*2]   = __float2bfloat16(ra[i].x - __bfloat162float(h0));
                Al[nb][row][acp*2+1] = __float2bfloat16(ra[i].y - __bfloat162float(h1));
            }
#pragma unroll
            for (int i = 0; i < 4; i++) {
                int row = arow + i*16;
                __nv_bfloat16 h0 = __float2bfloat16(rb[i].x);
                __nv_bfloat16 h1 = __float2bfloat16(rb[i].y);
                Bh[nb][row][acp*2]   = h0;
                Bh[nb][row][acp*2+1] = h1;
                Bl[nb][row][acp*2]   = __float2bfloat16(rb[i].x - __bfloat162float(h0));
                Bl[nb][row][acp*2+1] = __float2bfloat16(rb[i].y - __bfloat162float(h1));
            }
            __syncthreads();
        }
    }

    // ---- epilogue ----
#pragma unroll
    for (int i = 0; i < 2; i++) {
#pragma unroll
        for (int j = 0; j < 4; j++) {
            int mb = m0 + wm*32 + i*16 + grp;
            int nb = n0 + wn*32 + j*8 + tig*2;
            if (NEVEN) {
                if (nb < N) {
                    *(float2*)(C + (size_t)mb*N + nb)     = make_float2(acc[i][j][0], acc[i][j][1]);
                    *(float2*)(C + (size_t)(mb+8)*N + nb) = make_float2(acc[i][j][2], acc[i][j][3]);
                }
            } else {
                if (nb < N)     { C[(size_t)mb*N + nb]       = acc[i][j][0];
                                  C[(size_t)(mb+8)*N + nb]   = acc[i][j][2]; }
                if (nb + 1 < N) { C[(size_t)mb*N + nb+1]     = acc[i][j][1];
                                  C[(size_t)(mb+8)*N + nb+1] = acc[i][j][3]; }
            }
        }
    }
}

// -------- embedding lookup --------
__global__ void k_embed(const int* __restrict__ fasta, const float* __restrict__ emb) {
    int idx = blockIdx.x * blockDim.x + threadIdx.x;
    if (idx >= ROWS*DM) return;
    int r = idx / DM, m = idx - r*DM;
    g_hidden[idx] = emb[fasta[r]*DM + m];
}

// -------- residual add + rmsnorm --------
__global__ void k_addnorm(const float* __restrict__ nw, int first) {
    int row  = blockIdx.x * 8 + (threadIdx.x >> 5);
    int lane = threadIdx.x & 31;
    const float* hp = g_hidden + row*DM;
    float* rp = g_resid + row*DM;
    float v[6]; float ss = 0.f;
#pragma unroll
    for (int j = 0; j < 6; j++) {
        int i = lane + 32*j;
        float x = 0.f;
        if (i < DM) {
            x = hp[i];
            if (!first) x += rp[i];
            rp[i] = x;
        }
        v[j] = x; ss += x*x;
    }
#pragma unroll
    for (int o = 16; o; o >>= 1) ss += __shfl_xor_sync(0xffffffffu, ss, o);
    float sc = rsqrtf(ss * (1.f/DM) + EPSV);
    float* op = g_hnorm + row*DM;
#pragma unroll
    for (int j = 0; j < 6; j++) {
        int i = lane + 32*j;
        if (i < DM) op[i] = v[j] * sc * nw[i];
    }
}

// -------- final residual add + rmsnorm -> v --------
__global__ void k_finalnorm(const float* __restrict__ nfw, float* __restrict__ vout) {
    int row  = blockIdx.x * 8 + (threadIdx.x >> 5);
    int lane = threadIdx.x & 31;
    const float* hp = g_hidden + row*DM;
    const float* rp = g_resid  + row*DM;
    float v[6]; float ss = 0.f;
#pragma unroll
    for (int j = 0; j < 6; j++) {
        int i = lane + 32*j;
        float x = 0.f;
        if (i < DM) x = hp[i] + rp[i];
        v[j] = x; ss += x*x;
    }
#pragma unroll
    for (int o = 16; o; o >>= 1) ss += __shfl_xor_sync(0xffffffffu, ss, o);
    float sc = rsqrtf(ss * (1.f/DM) + EPSV);
    float* op = vout + row*DM;
#pragma unroll
    for (int j = 0; j < 6; j++) {
        int i = lane + 32*j;
        if (i < DM) op[i] = v[j] * sc * nfw[i];
    }
}

// -------- max over L --------
__global__ void k_maxL(const float* __restrict__ v, float* __restrict__ ve) {
    int w    = blockIdx.x * 8 + (threadIdx.x >> 5);
    int lane = threadIdx.x & 31;
    int b = w / DM, m = w - b*DM;
    float mx = -INFINITY;
    for (int l = lane; l < L_SZ; l += 32)
        mx = fmaxf(mx, v[(b*L_SZ + l)*DM + m]);
#pragma unroll
    for (int o = 16; o; o >>= 1) mx = fmaxf(mx, __shfl_xor_sync(0xffffffffu, mx, o));
    if (lane == 0) ve[b*DM + m] = mx;
}

// -------- causal depthwise conv (width 4) + SiLU --------
__global__ void k_conv(const float* __restrict__ cw, const float* __restrict__ cb) {
    int idx = blockIdx.x * blockDim.x + threadIdx.x;
    if (idx >= (ROWS/4)*DI) return;
    int d = idx % DI;
    int q = idx / DI;
    int b = q >> 8;
    int lq = (q & 255) << 2;
    const float* bp = g_xz + (size_t)b*L_SZ*XZW + d;
    float w0 = cw[d*4+0], w1 = cw[d*4+1], w2 = cw[d*4+2], w3 = cw[d*4+3];
    float bb = cb[d];
    float x[7];
    x[0] = (lq >= 3) ? bp[(lq-3)*XZW] : 0.f;
    x[1] = (lq >= 2) ? bp[(lq-2)*XZW] : 0.f;
    x[2] = (lq >= 1) ? bp[(lq-1)*XZW] : 0.f;
    x[3] = bp[(lq+0)*XZW];
    x[4] = bp[(lq+1)*XZW];
    x[5] = bp[(lq+2)*XZW];
    x[6] = bp[(lq+3)*XZW];
    float* op = g_xc + ((size_t)b*L_SZ + lq)*DI + d;
#pragma unroll
    for (int j = 0; j < 4; j++) {
        float s = bb;
        s = fmaf(w0, x[j],   s);
        s = fmaf(w1, x[j+1], s);
        s = fmaf(w2, x[j+2], s);
        s = fmaf(w3, x[j+3], s);
        op[j*DI] = fsilu(s);
    }
}

// -------- dt projection + softplus --------
__global__ void k_dtproj(const float* __restrict__ dtw, const float* __restrict__ dtb) {
    int idx = blockIdx.x * blockDim.x + threadIdx.x;
    if (idx >= ROWS*DI) return;
    int d = idx % DI;
    int row = idx / DI;
    const float* dbcp = g_dbc + row*DBCW;
    float acc = dtb[d];
#pragma unroll
    for (int k = 0; k < DTR; k++) acc = fmaf(dbcp[k], dtw[d*DTR + k], acc);
    g_dt[idx] = (acc > 15.f) ? acc : log1pf(__expf(acc));
}

// -------- chunked scan pass 1: per-segment (prodA, h from 0) --------
__global__ void k_scan1(const float* __restrict__ A_log) {
    int b = blockIdx.x;
    int s = blockIdx.z;
    int g = threadIdx.x >> 4;
    int n = threadIdx.x & 15;
    int d = blockIdx.y * 8 + g;
    bool valid = (d < DI);
    if (!valid) d = DI - 1;
    float A2 = -__expf(A_log[d*DS + n]) * LOG2E;
    float h = 0.f, P = 1.f;
    int row = b*L_SZ + s*SLEN;
#pragma unroll 4
    for (int l = 0; l < SLEN; l++) {
        float dtv = g_dt[row*DI + d];
        float xv  = g_xc[row*DI + d];
        float Bv  = g_dbc[row*DBCW + DTR + n];
        float dA = fex2(dtv * A2);
        h = fmaf(dA, h, dtv * xv * Bv);
        P *= dA;
        row++;
    }
    if (valid) {
        int idx = ((b*DI + d)*SEG + s)*DS + n;
        g_segP[idx] = P;
        g_segH[idx] = h;
    }
}

// -------- chunked scan pass 2: combine segment states --------
__global__ void k_scan2() {
    int idx = blockIdx.x * blockDim.x + threadIdx.x;
    if (idx >= B_SZ*DI*DS) return;
    int n = idx % DS;
    int bd = idx / DS;
    int base = bd*SEG*DS + n;
    float h = 0.f;
#pragma unroll
    for (int s = 0; s < SEG; s++) {
        g_segS[base + s*DS] = h;
        h = fmaf(g_segP[base + s*DS], h, g_segH[base + s*DS]);
    }
}

// -------- chunked scan pass 3: replay with y output --------
__global__ void k_scan3(const float* __restrict__ A_log, const float* __restrict__ Dp) {
    int b = blockIdx.x;
    int s = blockIdx.z;
    int g = threadIdx.x >> 4;
    int n = threadIdx.x & 15;
    int d = blockIdx.y * 8 + g;
    bool valid = (d < DI);
    if (!valid) d = DI - 1;
    float A2 = -__expf(A_log[d*DS + n]) * LOG2E;
    float Dv = Dp[d];
    float h = g_segS[((b*DI + d)*SEG + s)*DS + n];
    int row = b*L_SZ + s*SLEN;
    float dtv = g_dt[row*DI + d];
    float xv  = g_xc[row*DI + d];
    float Bv  = g_dbc[row*DBCW + DTR + n];
    float Cv  = g_dbc[row*DBCW + DTR + DS + n];
    float zv  = g_xz[row*XZW + DI + d];
#pragma unroll 4
    for (int l = 0; l < SLEN; l++) {
        int nrow = row + 1;
        float dtn = 0.f, xn = 0.f, Bn = 0.f, Cn = 0.f, zn = 0.f;
        if (l + 1 < SLEN) {
            dtn = g_dt[nrow*DI + d];
            xn  = g_xc[nrow*DI + d];
            Bn  = g_dbc[nrow*DBCW + DTR + n];
            Cn  = g_dbc[nrow*DBCW + DTR + DS + n];
            zn  = g_xz[nrow*XZW + DI + d];
        }
        float dA = fex2(dtv * A2);
        h = fmaf(dA, h, dtv * xv * Bv);
        float yp = h * Cv;
        yp += __shfl_xor_sync(0xffffffffu, yp, 8);
        yp += __shfl_xor_sync(0xffffffffu, yp, 4);
        yp += __shfl_xor_sync(0xffffffffu, yp, 2);
        yp += __shfl_xor_sync(0xffffffffu, yp, 1);
        if (n == 0 && valid) {
            g_y[row*DI + d] = fmaf(Dv, xv, yp) * fsilu(zv);
        }
        row = nrow;
        dtv = dtn; xv = xn; Bv = Bn; Cv = Cn; zv = zn;
    }
}

// ----------------------------------------------------------------------------
extern "C" void kernel_launch(void* const* d_in, const int* in_sizes, int n_in,
                              void* d_out, int out_size) {
    const int*   fasta = (const int*)  d_in[0];
    const float* emb   = (const float*)d_in[1];
    const float* in_w  = (const float*)d_in[2];
    const float* cw    = (const float*)d_in[3];
    const float* cb    = (const float*)d_in[4];
    const float* xw    = (const float*)d_in[5];
    const float* dtw   = (const float*)d_in[6];
    const float* dtb   = (const float*)d_in[7];
    const float* Alog  = (const float*)d_in[8];
    const float* Dp    = (const float*)d_in[9];
    const float* ow    = (const float*)d_in[10];
    const float* nw    = (const float*)d_in[11];
    const float* nfw   = (const float*)d_in[12];
    float* out = (float*)d_out;                   // [ve (16*166) | v (16*1024*166)]

    float *hn, *xz, *xc, *dbc, *y, *hid;
    cudaGetSymbolAddress((void**)&hn,  g_hnorm);
    cudaGetSymbolAddress((void**)&xz,  g_xz);
    cudaGetSymbolAddress((void**)&xc,  g_xc);
    cudaGetSymbolAddress((void**)&dbc, g_dbc);
    cudaGetSymbolAddress((void**)&y,   g_y);
    cudaGetSymbolAddress((void**)&hid, g_hidden);

    k_embed<<<(ROWS*DM + 255)/256, 256>>>(fasta, emb);

    for (int l = 0; l < NLAY; l++) {
        k_addnorm<<<ROWS/8, 256>>>(nw + l*DM, l == 0);
        // xz = hnorm @ in_w^T   (M=16384, N=664, K=166)
        k_hgemm<DM, true><<<dim3((XZW + BN - 1)/BN, ROWS/BM), 256>>>(hn, in_w + l*XZW*DM, xz, XZW);
        // conv + silu
        k_conv<<<((ROWS/4)*DI + 255)/256, 256>>>(cw + l*DI*DCV, cb + l*DI);
        // dbc = xc @ xw^T       (M=16384, N=43, K=332)
        k_hgemm<DI, false><<<dim3(1, ROWS/BM), 256>>>(xc, xw + l*DBCW*DI, dbc, DBCW);
        // dt = softplus(dbc[:, :11] @ dtw^T + dtb)
        k_dtproj<<<(ROWS*DI + 255)/256, 256>>>(dtw + l*DI*DTR, dtb + l*DI);
        // chunked selective scan
        k_scan1<<<dim3(B_SZ, (DI + 7)/8, SEG), 128>>>(Alog + l*DI*DS);
        k_scan2<<<(B_SZ*DI*DS + 255)/256, 256>>>();
        k_scan3<<<dim3(B_SZ, (DI + 7)/8, SEG), 128>>>(Alog + l*DI*DS, Dp + l*DI);
        // hidden = y @ ow^T     (M=16384, N=166, K=332)
        k_hgemm<DI, true><<<dim3((DM + BN - 1)/BN, ROWS/BM), 256>>>(y, ow + l*DM*DI, hid, DM);
    }

    k_finalnorm<<<ROWS/8, 256>>>(nfw, out + B_SZ*DM);
    k_maxL<<<(B_SZ*DM)/8, 256>>>(out + B_SZ*DM, out);
}

// round 7
// speedup vs baseline: 1.3340x; 1.3340x over previous
#include <cuda_runtime.h>
#include <cuda_bf16.h>
#include <math.h>
#include <stdint.h>

#define B_SZ  16
#define L_SZ  1024
#define DM    166
#define DI    332
#define DS    16
#define DCV   4
#define DTR   11
#define NLAY  3
#define XZW   (2*DI)        // 664
#define DBCW  (DTR + 2*DS)  // 43
#define ROWS  (B_SZ*L_SZ)   // 16384
#define EPSV  1e-5f
#define SEG   32
#define SLEN  (L_SZ/SEG)    // 32

// -------- scratch (device globals; no allocation allowed) --------
__device__ float g_hidden[ROWS*DM];
__device__ float g_resid [ROWS*DM];
__device__ float g_hnorm [ROWS*DM];
__device__ float g_xz    [ROWS*XZW];
__device__ float g_xc    [ROWS*DI];
__device__ float g_dbc   [ROWS*DBCW];
__device__ float g_y     [ROWS*DI];
__device__ float g_segP  [B_SZ*SEG*DI*DS];
__device__ float g_segH  [B_SZ*SEG*DI*DS];
__device__ float g_segS  [B_SZ*SEG*DI*DS];

// -------- fast transcendental helpers --------
__device__ __forceinline__ float fex2(float x) {
    float r; asm("ex2.approx.ftz.f32 %0, %1;" : "=f"(r) : "f"(x)); return r;
}
__device__ __forceinline__ float flg2(float x) {
    float r; asm("lg2.approx.ftz.f32 %0, %1;" : "=f"(r) : "f"(x)); return r;
}
__device__ __forceinline__ float frcp(float x) {
    float r; asm("rcp.approx.ftz.f32 %0, %1;" : "=f"(r) : "f"(x)); return r;
}
#define LOG2E 1.44269504f
#define LN2   0.69314718f
__device__ __forceinline__ float fsilu(float s) {
    return s * frcp(1.f + fex2(-LOG2E * s));
}
__device__ __forceinline__ float fsoftplus(float a) {
    return (a > 15.f) ? a : LN2 * flg2(1.f + fex2(a * LOG2E));
}

// ==================== split-bf16 HMMA GEMM (ldmatrix, single buffer) ====================
#define BM 128
#define BN 64
#define BK 32
#define LDK 40   // padded smem row (bf16): 80B stride -> conflict-free ldmatrix phases

__device__ __forceinline__ void mma_bf16(float* c, const uint32_t* a, uint32_t b0, uint32_t b1) {
    asm volatile(
        "mma.sync.aligned.m16n8k16.row.col.f32.bf16.bf16.f32 "
        "{%0,%1,%2,%3}, {%4,%5,%6,%7}, {%8,%9}, {%0,%1,%2,%3};"
        : "+f"(c[0]), "+f"(c[1]), "+f"(c[2]), "+f"(c[3])
        : "r"(a[0]), "r"(a[1]), "r"(a[2]), "r"(a[3]), "r"(b0), "r"(b1));
}
__device__ __forceinline__ void ldsm_x4(uint32_t* r, uint32_t addr) {
    asm volatile("ldmatrix.sync.aligned.m8n8.x4.shared.b16 {%0,%1,%2,%3}, [%4];"
        : "=r"(r[0]), "=r"(r[1]), "=r"(r[2]), "=r"(r[3]) : "r"(addr));
}

template<int K, bool NEVEN>
__global__ void __launch_bounds__(256) k_hgemm(const float* __restrict__ A,
                                               const float* __restrict__ W,
                                               float* __restrict__ C, int N) {
    __shared__ __nv_bfloat16 Ah[BM][LDK];
    __shared__ __nv_bfloat16 Al[BM][LDK];
    __shared__ __nv_bfloat16 Bh[BN][LDK];
    __shared__ __nv_bfloat16 Bl[BN][LDK];

    constexpr int KT = (K + BK - 1) / BK;
    int tid  = threadIdx.x;
    int wid  = tid >> 5;
    int lane = tid & 31;
    int wm = wid & 3;
    int wn = wid >> 2;
    int grp = lane >> 2;
    int tig = lane & 3;
    int m0 = blockIdx.y * BM;
    int n0 = blockIdx.x * BN;

    int arow = tid >> 4, acp = tid & 15;
    int lq = lane >> 3, lr = lane & 7;
    int frow = (lq & 1) * 8 + lr;
    int fcol = (lq >> 1) * 8;

    uint32_t sAh = (uint32_t)__cvta_generic_to_shared(&Ah[0][0]);
    uint32_t sAl = (uint32_t)__cvta_generic_to_shared(&Al[0][0]);
    uint32_t sBh = (uint32_t)__cvta_generic_to_shared(&Bh[0][0]);
    uint32_t sBl = (uint32_t)__cvta_generic_to_shared(&Bl[0][0]);

    float acc[2][4][4];
#pragma unroll
    for (int i = 0; i < 2; i++)
#pragma unroll
        for (int j = 0; j < 4; j++)
#pragma unroll
            for (int q = 0; q < 4; q++) acc[i][j][q] = 0.f;

    float2 ra[8], rb[4];

    // ---- prologue: load tile 0 into regs ----
#pragma unroll
    for (int i = 0; i < 8; i++) {
        int row = arow + i*16;
        int kg = acp*2;
        ra[i] = (kg < K) ? *(const float2*)(A + (size_t)(m0 + row)*K + kg)
                         : make_float2(0.f, 0.f);
    }
#pragma unroll
    for (int i = 0; i < 4; i++) {
        int row = arow + i*16;
        int kg = acp*2;
        int n = n0 + row;
        rb[i] = (n < N && kg < K) ? *(const float2*)(W + (size_t)n*K + kg)
                                  : make_float2(0.f, 0.f);
    }

#pragma unroll 1
    for (int t = 0; t < KT; t++) {
        // ---- split + store staged regs to smem ----
#pragma unroll
        for (int i = 0; i < 8; i++) {
            int row = arow + i*16;
            __nv_bfloat16 h0 = __float2bfloat16(ra[i].x);
            __nv_bfloat16 h1 = __float2bfloat16(ra[i].y);
            Ah[row][acp*2]   = h0;
            Ah[row][acp*2+1] = h1;
            Al[row][acp*2]   = __float2bfloat16(ra[i].x - __bfloat162float(h0));
            Al[row][acp*2+1] = __float2bfloat16(ra[i].y - __bfloat162float(h1));
        }
#pragma unroll
        for (int i = 0; i < 4; i++) {
            int row = arow + i*16;
            __nv_bfloat16 h0 = __float2bfloat16(rb[i].x);
            __nv_bfloat16 h1 = __float2bfloat16(rb[i].y);
            Bh[row][acp*2]   = h0;
            Bh[row][acp*2+1] = h1;
            Bl[row][acp*2]   = __float2bfloat16(rb[i].x - __bfloat162float(h0));
            Bl[row][acp*2+1] = __float2bfloat16(rb[i].y - __bfloat162float(h1));
        }
        __syncthreads();

        // ---- issue next tile's LDGs (overlapped with MMA below) ----
        if (t + 1 < KT) {
            int k0 = (t + 1) * BK;
#pragma unroll
            for (int i = 0; i < 8; i++) {
                int row = arow + i*16;
                int kg = k0 + acp*2;
                ra[i] = (kg < K) ? *(const float2*)(A + (size_t)(m0 + row)*K + kg)
                                 : make_float2(0.f, 0.f);
            }
#pragma unroll
            for (int i = 0; i < 4; i++) {
                int row = arow + i*16;
                int kg = k0 + acp*2;
                int n = n0 + row;
                rb[i] = (n < N && kg < K) ? *(const float2*)(W + (size_t)n*K + kg)
                                          : make_float2(0.f, 0.f);
            }
        }

        // ---- compute via ldmatrix ----
#pragma unroll
        for (int ks = 0; ks < BK; ks += 16) {
            uint32_t ah[2][4], al[2][4], bh[2][4], bl[2][4];
#pragma unroll
            for (int i = 0; i < 2; i++) {
                uint32_t ro = (uint32_t)((wm*32 + i*16 + frow)*LDK + ks + fcol)*2;
                ldsm_x4(ah[i], sAh + ro);
                ldsm_x4(al[i], sAl + ro);
            }
#pragma unroll
            for (int jj = 0; jj < 2; jj++) {
                uint32_t ro = (uint32_t)((wn*32 + jj*16 + frow)*LDK + ks + fcol)*2;
                ldsm_x4(bh[jj], sBh + ro);
                ldsm_x4(bl[jj], sBl + ro);
            }
#pragma unroll
            for (int i = 0; i < 2; i++)
#pragma unroll
                for (int j = 0; j < 4; j++) {
                    int jj = j >> 1, sel = j & 1;
                    uint32_t b0h = bh[jj][sel], b1h = bh[jj][sel + 2];
                    uint32_t b0l = bl[jj][sel], b1l = bl[jj][sel + 2];
                    mma_bf16(acc[i][j], ah[i], b0h, b1h);
                    mma_bf16(acc[i][j], ah[i], b0l, b1l);
                    mma_bf16(acc[i][j], al[i], b0h, b1h);
                }
        }
        __syncthreads();
    }

    // ---- epilogue ----
#pragma unroll
    for (int i = 0; i < 2; i++) {
#pragma unroll
        for (int j = 0; j < 4; j++) {
            int mb = m0 + wm*32 + i*16 + grp;
            int nb = n0 + wn*32 + j*8 + tig*2;
            if (NEVEN) {
                if (nb < N) {
                    *(float2*)(C + (size_t)mb*N + nb)     = make_float2(acc[i][j][0], acc[i][j][1]);
                    *(float2*)(C + (size_t)(mb+8)*N + nb) = make_float2(acc[i][j][2], acc[i][j][3]);
                }
            } else {
                if (nb < N)     { C[(size_t)mb*N + nb]       = acc[i][j][0];
                                  C[(size_t)(mb+8)*N + nb]   = acc[i][j][2]; }
                if (nb + 1 < N) { C[(size_t)mb*N + nb+1]     = acc[i][j][1];
                                  C[(size_t)(mb+8)*N + nb+1] = acc[i][j][3]; }
            }
        }
    }
}

// -------- embedding lookup --------
__global__ void k_embed(const int* __restrict__ fasta, const float* __restrict__ emb) {
    int idx = blockIdx.x * blockDim.x + threadIdx.x;
    if (idx >= ROWS*DM) return;
    int r = idx / DM, m = idx - r*DM;
    g_hidden[idx] = emb[fasta[r]*DM + m];
}

// -------- residual add + rmsnorm --------
__global__ void k_addnorm(const float* __restrict__ nw, int first) {
    int row  = blockIdx.x * 8 + (threadIdx.x >> 5);
    int lane = threadIdx.x & 31;
    const float* hp = g_hidden + row*DM;
    float* rp = g_resid + row*DM;
    float v[6]; float ss = 0.f;
#pragma unroll
    for (int j = 0; j < 6; j++) {
        int i = lane + 32*j;
        float x = 0.f;
        if (i < DM) {
            x = hp[i];
            if (!first) x += rp[i];
            rp[i] = x;
        }
        v[j] = x; ss += x*x;
    }
#pragma unroll
    for (int o = 16; o; o >>= 1) ss += __shfl_xor_sync(0xffffffffu, ss, o);
    float sc = rsqrtf(ss * (1.f/DM) + EPSV);
    float* op = g_hnorm + row*DM;
#pragma unroll
    for (int j = 0; j < 6; j++) {
        int i = lane + 32*j;
        if (i < DM) op[i] = v[j] * sc * nw[i];
    }
}

// -------- final residual add + rmsnorm -> v --------
__global__ void k_finalnorm(const float* __restrict__ nfw, float* __restrict__ vout) {
    int row  = blockIdx.x * 8 + (threadIdx.x >> 5);
    int lane = threadIdx.x & 31;
    const float* hp = g_hidden + row*DM;
    const float* rp = g_resid  + row*DM;
    float v[6]; float ss = 0.f;
#pragma unroll
    for (int j = 0; j < 6; j++) {
        int i = lane + 32*j;
        float x = 0.f;
        if (i < DM) x = hp[i] + rp[i];
        v[j] = x; ss += x*x;
    }
#pragma unroll
    for (int o = 16; o; o >>= 1) ss += __shfl_xor_sync(0xffffffffu, ss, o);
    float sc = rsqrtf(ss * (1.f/DM) + EPSV);
    float* op = vout + row*DM;
#pragma unroll
    for (int j = 0; j < 6; j++) {
        int i = lane + 32*j;
        if (i < DM) op[i] = v[j] * sc * nfw[i];
    }
}

// -------- max over L --------
__global__ void k_maxL(const float* __restrict__ v, float* __restrict__ ve) {
    int w    = blockIdx.x * 8 + (threadIdx.x >> 5);
    int lane = threadIdx.x & 31;
    int b = w / DM, m = w - b*DM;
    float mx = -INFINITY;
    for (int l = lane; l < L_SZ; l += 32)
        mx = fmaxf(mx, v[(b*L_SZ + l)*DM + m]);
#pragma unroll
    for (int o = 16; o; o >>= 1) mx = fmaxf(mx, __shfl_xor_sync(0xffffffffu, mx, o));
    if (lane == 0) ve[b*DM + m] = mx;
}

// -------- causal depthwise conv (width 4) + SiLU --------
__global__ void k_conv(const float* __restrict__ cw, const float* __restrict__ cb) {
    int idx = blockIdx.x * blockDim.x + threadIdx.x;
    if (idx >= (ROWS/4)*DI) return;
    int d = idx % DI;
    int q = idx / DI;
    int b = q >> 8;
    int lq = (q & 255) << 2;
    const float* bp = g_xz + (size_t)b*L_SZ*XZW + d;
    float w0 = cw[d*4+0], w1 = cw[d*4+1], w2 = cw[d*4+2], w3 = cw[d*4+3];
    float bb = cb[d];
    float x[7];
    x[0] = (lq >= 3) ? bp[(lq-3)*XZW] : 0.f;
    x[1] = (lq >= 2) ? bp[(lq-2)*XZW] : 0.f;
    x[2] = (lq >= 1) ? bp[(lq-1)*XZW] : 0.f;
    x[3] = bp[(lq+0)*XZW];
    x[4] = bp[(lq+1)*XZW];
    x[5] = bp[(lq+2)*XZW];
    x[6] = bp[(lq+3)*XZW];
    float* op = g_xc + ((size_t)b*L_SZ + lq)*DI + d;
#pragma unroll
    for (int j = 0; j < 4; j++) {
        float s = bb;
        s = fmaf(w0, x[j],   s);
        s = fmaf(w1, x[j+1], s);
        s = fmaf(w2, x[j+2], s);
        s = fmaf(w3, x[j+3], s);
        op[j*DI] = fsilu(s);
    }
}

// -------- scan pass 1: register-resident, fused dt-projection --------
// thread = (b, s, d): all 16 states in registers; writes (P, H) per segment.
__global__ void __launch_bounds__(128) k_scan1(const float* __restrict__ A_log,
                                               const float* __restrict__ dtw,
                                               const float* __restrict__ dtb) {
    int d  = blockIdx.x * 128 + threadIdx.x;
    int bs = blockIdx.y;
    int b = bs >> 5, s = bs & 31;
    if (d >= DI) return;

    float A2[DS];
#pragma unroll
    for (int n = 0; n < DS; n++) A2[n] = -__expf(A_log[d*DS + n]) * LOG2E;
    float wv[DTR];
#pragma unroll
    for (int k = 0; k < DTR; k++) wv[k] = dtw[d*DTR + k];
    float bias = dtb[d];

    float h[DS], P[DS];
#pragma unroll
    for (int n = 0; n < DS; n++) { h[n] = 0.f; P[n] = 1.f; }

    int row = b*L_SZ + s*SLEN;
#pragma unroll 2
    for (int l = 0; l < SLEN; l++) {
        const float* dbcp = g_dbc + row*DBCW;   // warp-uniform row
        float acc = bias;
#pragma unroll
        for (int k = 0; k < DTR; k++) acc = fmaf(dbcp[k], wv[k], acc);
        float dt = fsoftplus(acc);
        float xv = g_xc[row*DI + d];
        float dtx = dt * xv;
#pragma unroll
        for (int n = 0; n < DS; n++) {
            float dA = fex2(dt * A2[n]);
            h[n] = fmaf(dA, h[n], dtx * dbcp[DTR + n]);
            P[n] *= dA;
        }
        row++;
    }
    int o = ((bs)*DI + d) * DS;   // layout (b,s,d,n): coalesced across d
#pragma unroll
    for (int n = 0; n < DS; n += 4) {
        *(float4*)(g_segH + o + n) = make_float4(h[n], h[n+1], h[n+2], h[n+3]);
        *(float4*)(g_segP + o + n) = make_float4(P[n], P[n+1], P[n+2], P[n+3]);
    }
}

// -------- scan pass 2: combine segment states (thread per (b,d,n)) --------
__global__ void k_scan2() {
    int idx = blockIdx.x * blockDim.x + threadIdx.x;
    if (idx >= B_SZ*DI*DS) return;
    int dn = idx % (DI*DS);       // d*DS + n
    int b  = idx / (DI*DS);
    float h = 0.f;
#pragma unroll
    for (int s = 0; s < SEG; s++) {
        int pos = ((b*SEG + s)*DI)*DS + dn;
        g_segS[pos] = h;
        h = fmaf(g_segP[pos], h, g_segH[pos]);
    }
}

// -------- scan pass 3: replay with fused dt, y = (h.C + D*x)*silu(z) --------
__global__ void __launch_bounds__(128) k_scan3(const float* __restrict__ A_log,
                                               const float* __restrict__ dtw,
                                               const float* __restrict__ dtb,
                                               const float* __restrict__ Dp) {
    int d  = blockIdx.x * 128 + threadIdx.x;
    int bs = blockIdx.y;
    int b = bs >> 5, s = bs & 31;
    if (d >= DI) return;

    float A2[DS];
#pragma unroll
    for (int n = 0; n < DS; n++) A2[n] = -__expf(A_log[d*DS + n]) * LOG2E;
    float wv[DTR];
#pragma unroll
    for (int k = 0; k < DTR; k++) wv[k] = dtw[d*DTR + k];
    float bias = dtb[d];
    float Dv = Dp[d];

    float h[DS];
    {
        int o = (bs*DI + d) * DS;
#pragma unroll
        for (int n = 0; n < DS; n += 4) {
            float4 v = *(const float4*)(g_segS + o + n);
            h[n] = v.x; h[n+1] = v.y; h[n+2] = v.z; h[n+3] = v.w;
        }
    }

    int row = b*L_SZ + s*SLEN;
#pragma unroll 2
    for (int l = 0; l < SLEN; l++) {
        const float* dbcp = g_dbc + row*DBCW;
        float acc = bias;
#pragma unroll
        for (int k = 0; k < DTR; k++) acc = fmaf(dbcp[k], wv[k], acc);
        float dt = fsoftplus(acc);
        float xv = g_xc[row*DI + d];
        float zv = g_xz[row*XZW + DI + d];
        float dtx = dt * xv;
        float yp = 0.f;
#pragma unroll
        for (int n = 0; n < DS; n++) {
            float dA = fex2(dt * A2[n]);
            h[n] = fmaf(dA, h[n], dtx * dbcp[DTR + n]);
            yp = fmaf(h[n], dbcp[DTR + DS + n], yp);
        }
        g_y[row*DI + d] = fmaf(Dv, xv, yp) * fsilu(zv);
        row++;
    }
}

// ----------------------------------------------------------------------------
extern "C" void kernel_launch(void* const* d_in, const int* in_sizes, int n_in,
                              void* d_out, int out_size) {
    const int*   fasta = (const int*)  d_in[0];
    const float* emb   = (const float*)d_in[1];
    const float* in_w  = (const float*)d_in[2];
    const float* cw    = (const float*)d_in[3];
    const float* cb    = (const float*)d_in[4];
    const float* xw    = (const float*)d_in[5];
    const float* dtw   = (const float*)d_in[6];
    const float* dtb   = (const float*)d_in[7];
    const float* Alog  = (const float*)d_in[8];
    const float* Dp    = (const float*)d_in[9];
    const float* ow    = (const float*)d_in[10];
    const float* nw    = (const float*)d_in[11];
    const float* nfw   = (const float*)d_in[12];
    float* out = (float*)d_out;                   // [ve (16*166) | v (16*1024*166)]

    float *hn, *xz, *xc, *dbc, *y, *hid;
    cudaGetSymbolAddress((void**)&hn,  g_hnorm);
    cudaGetSymbolAddress((void**)&xz,  g_xz);
    cudaGetSymbolAddress((void**)&xc,  g_xc);
    cudaGetSymbolAddress((void**)&dbc, g_dbc);
    cudaGetSymbolAddress((void**)&y,   g_y);
    cudaGetSymbolAddress((void**)&hid, g_hidden);

    k_embed<<<(ROWS*DM + 255)/256, 256>>>(fasta, emb);

    dim3 sgrid((DI + 127)/128, B_SZ*SEG);

    for (int l = 0; l < NLAY; l++) {
        k_addnorm<<<ROWS/8, 256>>>(nw + l*DM, l == 0);
        // xz = hnorm @ in_w^T   (M=16384, N=664, K=166)
        k_hgemm<DM, true><<<dim3((XZW + BN - 1)/BN, ROWS/BM), 256>>>(hn, in_w + l*XZW*DM, xz, XZW);
        // conv + silu
        k_conv<<<((ROWS/4)*DI + 255)/256, 256>>>(cw + l*DI*DCV, cb + l*DI);
        // dbc = xc @ xw^T       (M=16384, N=43, K=332)
        k_hgemm<DI, false><<<dim3(1, ROWS/BM), 256>>>(xc, xw + l*DBCW*DI, dbc, DBCW);
        // chunked selective scan (dt-projection fused)
        k_scan1<<<sgrid, 128>>>(Alog + l*DI*DS, dtw + l*DI*DTR, dtb + l*DI);
        k_scan2<<<(B_SZ*DI*DS + 255)/256, 256>>>();
        k_scan3<<<sgrid, 128>>>(Alog + l*DI*DS, dtw + l*DI*DTR, dtb + l*DI, Dp + l*DI);
        // hidden = y @ ow^T     (M=16384, N=166, K=332)
        k_hgemm<DI, true><<<dim3((DM + BN - 1)/BN, ROWS/BM), 256>>>(y, ow + l*DM*DI, hid, DM);
    }

    k_finalnorm<<<ROWS/8, 256>>>(nfw, out + B_SZ*DM);
    k_maxL<<<(B_SZ*DM)/8, 256>>>(out + B_SZ*DM, out);
}